// round 7
// baseline (speedup 1.0000x reference)
#include <cuda_runtime.h>
#include <cstdint>
#include <cstddef>

// Problem constants: B=4, C=128, N=64, HID=1536, PROJ=768
// feat: [768, 128], h: [768, 1536], out: [768, 768]

__device__ float g_feat[768 * 128];
__device__ float g_hbuf[768 * 1536];
__device__ float g_part[4 * 768 * 768];

__device__ __forceinline__ void redadd(float* p, float v) {
    asm volatile("red.global.add.f32 [%0], %1;" :: "l"(p), "f"(v) : "memory");
}

// ---------------------------------------------------------------------------
__global__ void __launch_bounds__(256) init_feat() {
    const int i = blockIdx.x * 256 + threadIdx.x;   // 24576 float4
    reinterpret_cast<float4*>(g_feat)[i] = make_float4(0.f, 0.f, 0.f, 0.f);
}

// ---------------------------------------------------------------------------
// Kernel 1: streaming reduction, 4096 CTAs (1/8 slab = 8 d-planes, 128 KB).
// (unchanged from R6 — hit its DRAM prediction)
// ---------------------------------------------------------------------------
__global__ void __launch_bounds__(256, 4) reduce_kernel(const float* __restrict__ x) {
    __shared__ float dpart[8 * 64];
    __shared__ float ss_s[64];
    __shared__ float sa_s[64];
    const int tid = threadIdx.x;
    if (tid < 64) { ss_s[tid] = 0.f; sa_s[tid] = 0.f; }
    __syncthreads();

    const int slab = blockIdx.x >> 3;
    const int p    = blockIdx.x & 7;
    const int warp = tid >> 5;
    const int lane = tid & 31;
    const int q    = warp & 3;
    const int half = warp >> 2;
    const int j    = lane & 15;
    const int u    = lane >> 4;

    const float4* base = reinterpret_cast<const float4*>(x) + (size_t)slab * 65536
                         + (size_t)(8 * p) * 1024 + (16 * q + u) * 16 + j;

    float hreg[8];
#pragma unroll
    for (int i = 0; i < 8; ++i) hreg[i] = 0.f;
    float w0 = 0.f, w1 = 0.f, w2 = 0.f, w3 = 0.f;

#pragma unroll
    for (int dd = 0; dd < 4; ++dd) {
        const int dl = 2 * dd + half;
        const float4* pp = base + dl * 1024;
        float dacc = 0.f;
#pragma unroll
        for (int i = 0; i < 8; ++i) {
            float4 v = __ldcs(pp + i * 32);
            float s0 = v.x * v.x, s1 = v.y * v.y, s2 = v.z * v.z, s3 = v.w * v.w;
            w0 += s0; w1 += s1; w2 += s2; w3 += s3;
            float sm = (s0 + s1) + (s2 + s3);
            hreg[i] += sm;
            dacc    += sm;
        }
        dacc += __shfl_xor_sync(0xffffffffu, dacc, 16);
        if (lane < 16) dpart[dl * 64 + q * 16 + j] = dacc;
    }

#pragma unroll
    for (int i = 0; i < 8; ++i) {
        float v = hreg[i];
        v += __shfl_xor_sync(0xffffffffu, v, 1);
        v += __shfl_xor_sync(0xffffffffu, v, 2);
        v += __shfl_xor_sync(0xffffffffu, v, 4);
        v += __shfl_xor_sync(0xffffffffu, v, 8);
        if (j == 0) atomicAdd(&ss_s[16 * q + u + 2 * i], v);
    }

    atomicAdd(&sa_s[4 * j + 0], w0);
    atomicAdd(&sa_s[4 * j + 1], w1);
    atomicAdd(&sa_s[4 * j + 2], w2);
    atomicAdd(&sa_s[4 * j + 3], w3);

    __syncthreads();

    const int b = slab >> 7;
    const int c = slab & 127;
    if (tid < 32) {
        const int dl = tid >> 2;
        const int qq = tid & 3;
        const float4* dp = reinterpret_cast<const float4*>(&dpart[dl * 64 + qq * 16]);
        float s = 0.f;
#pragma unroll
        for (int k = 0; k < 4; ++k) {
            float4 v = dp[k];
            s += (v.x + v.y) + (v.z + v.w);
        }
        s += __shfl_xor_sync(0xffffffffu, s, 1);
        s += __shfl_xor_sync(0xffffffffu, s, 2);
        if (qq == 0)
            g_feat[(size_t)(b * 192 + 8 * p + dl) * 128 + c] = s * (1.0f / 4096.0f);
    }
    if (tid < 64) {
        redadd(&g_feat[(size_t)(b * 192 + 64 + tid) * 128 + c],
               ss_s[tid] * (1.0f / 4096.0f));
    } else if (tid < 128) {
        const int t = tid - 64;
        redadd(&g_feat[(size_t)(b * 192 + 128 + t) * 128 + c],
               sa_s[t] * (1.0f / 4096.0f));
    }
}

// ---------------------------------------------------------------------------
// FFMA2 SGEMM: tile (64*GM) x 64, BK=16, 256 threads, (4*GM)m x 4n microtile.
// 288-CTA grids -> 2 CTAs/SM resident -> 4 warps/SMSP (hides LDS latency).
// A smem [k][64*GM (+4 pad)]: LDS.128 yields natural f32x2 m-pairs;
// B smem [k][64] filled by cp.async (no staging regs); 4 n-scalars packed
// (b,b) by ALU movs. Per k-step/warp: (GM+1) LDS.128 + 4 MOV + 8*GM FFMA2.
// Double-buffered: cp.async(B,t+1) + LDG(A,t+1) issued before compute(t).
// GEMM1 (GM=1): epilogue bias+relu. GEMM2 (GM=2): partials at C + z*768*768.
// ---------------------------------------------------------------------------
__device__ __forceinline__ void fma2(unsigned long long& d,
                                     unsigned long long a,
                                     unsigned long long b) {
    asm("fma.rn.f32x2 %0, %1, %2, %0;" : "+l"(d) : "l"(a), "l"(b));
}
__device__ __forceinline__ unsigned long long pack2(float v) {
    unsigned long long r;
    asm("mov.b64 %0, {%1, %1};" : "=l"(r) : "f"(v));
    return r;
}
__device__ __forceinline__ float2 u2f(unsigned long long v) {
    float2 f;
    asm("mov.b64 {%0,%1}, %2;" : "=f"(f.x), "=f"(f.y) : "l"(v));
    return f;
}
__device__ __forceinline__ void cp_async16(uint32_t dst, const void* src) {
    asm volatile("cp.async.ca.shared.global [%0], [%1], 16;"
                 :: "r"(dst), "l"(src) : "memory");
}

template <int GM, bool GEMM1>
__global__ void __launch_bounds__(256) gemm_kernel(const float* __restrict__ A,
                                                   const float* __restrict__ Bw,
                                                   const float* __restrict__ bias,
                                                   float* __restrict__ C,
                                                   int Nn, int K, int Kc) {
    constexpr int ASTRIDE = 64 * GM + 4;          // floats per k-row (padded)
    constexpr int ASTAGE_B = 16 * ASTRIDE * 4;    // bytes per stage
    __shared__ float As[2][16][ASTRIDE];
    __shared__ float Bs[2][16][64];

    const int tid = threadIdx.x;
    const int tx = tid & 15;
    const int ty = tid >> 4;
    const int m0 = blockIdx.y * (64 * GM);
    const int n0 = blockIdx.x * 64;
    const int kstart = blockIdx.z * Kc;
    const int T = Kc >> 4;

    unsigned long long acc[2 * GM][4];
#pragma unroll
    for (int i = 0; i < 2 * GM; ++i)
#pragma unroll
        for (int qn = 0; qn < 4; ++qn) acc[i][qn] = 0ull;

    // staging assignments
    const int a_m = tid >> 2;           // 0..63 (per m-group)
    const int a_f4 = tid & 3;           // f4 index within 16-k row
    const int b_k = tid >> 4;           // 0..15
    const int b_n4 = tid & 15;          // f4 col

    const float* Ap[GM];
#pragma unroll
    for (int r = 0; r < GM; ++r)
        Ap[r] = A + (size_t)(m0 + 64 * r + a_m) * K + kstart + 4 * a_f4;
    const float* Bp = Bw + (size_t)(kstart + b_k) * Nn + n0 + 4 * b_n4;

    const unsigned as_base = (unsigned)__cvta_generic_to_shared(&As[0][0][0]);
    const unsigned bs_base = (unsigned)__cvta_generic_to_shared(&Bs[0][0][0]);
    const unsigned a_rd = as_base + (unsigned)(ty * 16);
    const unsigned b_rd = bs_base + (unsigned)(tx * 16);
    const unsigned b_wr = bs_base + (unsigned)(b_k * 256 + b_n4 * 16);
    const unsigned a_wr = as_base + (unsigned)((4 * a_f4) * ASTRIDE * 4 + a_m * 4);

    // prologue: tile 0
    cp_async16(b_wr, Bp);
    asm volatile("cp.async.commit_group;" ::: "memory");
    float4 pa[GM];
#pragma unroll
    for (int r = 0; r < GM; ++r) pa[r] = *reinterpret_cast<const float4*>(Ap[r]);
#pragma unroll
    for (int r = 0; r < GM; ++r) {
        float* aw = &As[0][0][0] + (4 * a_f4) * ASTRIDE + (64 * r + a_m);
        aw[0]           = pa[r].x;
        aw[ASTRIDE]     = pa[r].y;
        aw[2 * ASTRIDE] = pa[r].z;
        aw[3 * ASTRIDE] = pa[r].w;
    }
    asm volatile("cp.async.wait_group 0;" ::: "memory");
    __syncthreads();

    for (int t = 0; ; ) {
        const int st = t & 1;
        const int ns = st ^ 1;
        const bool more = (t + 1 < T);
        if (more) {
            cp_async16(b_wr + (unsigned)(ns * 4096),
                       Bp + (size_t)(t + 1) * 16 * Nn);
            asm volatile("cp.async.commit_group;" ::: "memory");
#pragma unroll
            for (int r = 0; r < GM; ++r)
                pa[r] = *reinterpret_cast<const float4*>(Ap[r] + (t + 1) * 16);
        }

        const unsigned ao = a_rd + (unsigned)(st * ASTAGE_B);
        const unsigned bo = b_rd + (unsigned)(st * 4096);
#pragma unroll
        for (int k = 0; k < 16; ++k) {
            unsigned long long am[2 * GM];
            float bf[4];
#pragma unroll
            for (int g = 0; g < GM; ++g)
                asm volatile("ld.shared.v2.b64 {%0,%1},[%2];"
                             : "=l"(am[2 * g]), "=l"(am[2 * g + 1])
                             : "r"(ao + (unsigned)(k * ASTRIDE * 4 + g * 256)));
            asm volatile("ld.shared.v4.f32 {%0,%1,%2,%3},[%4];"
                         : "=f"(bf[0]), "=f"(bf[1]), "=f"(bf[2]), "=f"(bf[3])
                         : "r"(bo + (unsigned)(k * 256)));
            unsigned long long bb[4];
#pragma unroll
            for (int qn = 0; qn < 4; ++qn) bb[qn] = pack2(bf[qn]);
#pragma unroll
            for (int i = 0; i < 2 * GM; ++i) {
#pragma unroll
                for (int qn = 0; qn < 4; ++qn) fma2(acc[i][qn], am[i], bb[qn]);
            }
        }

        if (!more) break;
#pragma unroll
        for (int r = 0; r < GM; ++r) {
            float* aw = &As[ns][0][0] + (4 * a_f4) * ASTRIDE + (64 * r + a_m);
            aw[0]           = pa[r].x;
            aw[ASTRIDE]     = pa[r].y;
            aw[2 * ASTRIDE] = pa[r].z;
            aw[3 * ASTRIDE] = pa[r].w;
        }
        asm volatile("cp.async.wait_group 0;" ::: "memory");
        __syncthreads();
        ++t;
    }

    // epilogue: acc[i][qn], i = 2g+p -> rows m0 + 64g + 4ty + 2p (+1 for .y),
    // cols n0 + 4tx + qn.
    if (GEMM1) {
        float4 bl = *reinterpret_cast<const float4*>(&bias[n0 + 4 * tx]);
#pragma unroll
        for (int i = 0; i < 2 * GM; ++i) {
            const int mrow = m0 + 64 * (i >> 1) + 4 * ty + 2 * (i & 1);
            float2 f[4];
#pragma unroll
            for (int qn = 0; qn < 4; ++qn) f[qn] = u2f(acc[i][qn]);
            float4 lo0 = make_float4(fmaxf(f[0].x + bl.x, 0.f), fmaxf(f[1].x + bl.y, 0.f),
                                     fmaxf(f[2].x + bl.z, 0.f), fmaxf(f[3].x + bl.w, 0.f));
            float4 lo1 = make_float4(fmaxf(f[0].y + bl.x, 0.f), fmaxf(f[1].y + bl.y, 0.f),
                                     fmaxf(f[2].y + bl.z, 0.f), fmaxf(f[3].y + bl.w, 0.f));
            *reinterpret_cast<float4*>(&C[(size_t)mrow * Nn + n0 + 4 * tx]) = lo0;
            *reinterpret_cast<float4*>(&C[(size_t)(mrow + 1) * Nn + n0 + 4 * tx]) = lo1;
        }
    } else {
        float* Cout = C + (size_t)blockIdx.z * 768 * 768;
#pragma unroll
        for (int i = 0; i < 2 * GM; ++i) {
            const int mrow = m0 + 64 * (i >> 1) + 4 * ty + 2 * (i & 1);
            float2 f[4];
#pragma unroll
            for (int qn = 0; qn < 4; ++qn) f[qn] = u2f(acc[i][qn]);
            float4 lo0 = make_float4(f[0].x, f[1].x, f[2].x, f[3].x);
            float4 lo1 = make_float4(f[0].y, f[1].y, f[2].y, f[3].y);
            *reinterpret_cast<float4*>(&Cout[(size_t)mrow * Nn + n0 + 4 * tx]) = lo0;
            *reinterpret_cast<float4*>(&Cout[(size_t)(mrow + 1) * Nn + n0 + 4 * tx]) = lo1;
        }
    }
}

// ---------------------------------------------------------------------------
// Combine split-K=4 partials + bias; 2 float4/thread (MLP 8).
// ---------------------------------------------------------------------------
__global__ void __launch_bounds__(256) combine_kernel(const float* __restrict__ part,
                                                      const float* __restrict__ bias,
                                                      float* __restrict__ out) {
    const float4* p = reinterpret_cast<const float4*>(part);
#pragma unroll
    for (int rep = 0; rep < 2; ++rep) {
        const int i = blockIdx.x * 512 + rep * 256 + threadIdx.x;
        float4 a = p[i];
        float4 b = p[i + 147456];
        float4 cc = p[i + 2 * 147456];
        float4 d = p[i + 3 * 147456];
        float4 bb = reinterpret_cast<const float4*>(bias)[i % 192];
        float4 r;
        r.x = ((a.x + b.x) + (cc.x + d.x)) + bb.x;
        r.y = ((a.y + b.y) + (cc.y + d.y)) + bb.y;
        r.z = ((a.z + b.z) + (cc.z + d.z)) + bb.z;
        r.w = ((a.w + b.w) + (cc.w + d.w)) + bb.w;
        reinterpret_cast<float4*>(out)[i] = r;
    }
}

// ---------------------------------------------------------------------------
extern "C" void kernel_launch(void* const* d_in, const int* in_sizes, int n_in,
                              void* d_out, int out_size) {
    const float* x  = (const float*)d_in[0];
    const float* W1 = (const float*)d_in[1];
    const float* b1 = (const float*)d_in[2];
    const float* W2 = (const float*)d_in[3];
    const float* b2 = (const float*)d_in[4];
    float* out = (float*)d_out;

    float* feat = nullptr;
    float* hbuf = nullptr;
    float* part = nullptr;
    cudaGetSymbolAddress((void**)&feat, g_feat);
    cudaGetSymbolAddress((void**)&hbuf, g_hbuf);
    cudaGetSymbolAddress((void**)&part, g_part);

    // 0) zero g_feat (h/w planes are RED targets)
    init_feat<<<96, 256>>>();

    // 1) reduction: 4096 CTAs (1/8 slab each)
    reduce_kernel<<<4096, 256>>>(x);

    // 2) h = relu(feat @ W1 + b1): tile 64x64 -> grid 24x12 = 288 CTAs
    gemm_kernel<1, true><<<dim3(24, 12, 1), 256>>>(feat, W1, b1, hbuf,
                                                   1536, 128, 128);

    // 3) partials = h @ W2 (split-K=4): tile 128x64 -> 12x6x4 = 288 CTAs
    gemm_kernel<2, false><<<dim3(12, 6, 4), 256>>>(hbuf, W2, nullptr, part,
                                                   768, 1536, 384);

    // 4) out = sum(partials) + b2
    combine_kernel<<<288, 256>>>(part, b2, out);
}

// round 8
// speedup vs baseline: 1.0303x; 1.0303x over previous
#include <cuda_runtime.h>
#include <cstdint>
#include <cstddef>

// Problem constants: B=4, C=128, N=64, HID=1536, PROJ=768
// feat: [768, 128], h: [768, 1536], out: [768, 768]

__device__ float g_feat[768 * 128];
__device__ float g_hbuf[768 * 1536];
__device__ float g_part[8 * 768 * 768];

__device__ __forceinline__ void redadd(float* p, float v) {
    asm volatile("red.global.add.f32 [%0], %1;" :: "l"(p), "f"(v) : "memory");
}

// ---------------------------------------------------------------------------
__global__ void __launch_bounds__(256) init_feat() {
    const int i = blockIdx.x * 256 + threadIdx.x;   // 24576 float4
    reinterpret_cast<float4*>(g_feat)[i] = make_float4(0.f, 0.f, 0.f, 0.f);
}

// ---------------------------------------------------------------------------
// Kernel 1: streaming reduction, 4096 CTAs (1/8 slab = 8 d-planes, 128 KB).
// (unchanged — meets its DRAM-bound prediction)
// ---------------------------------------------------------------------------
__global__ void __launch_bounds__(256, 4) reduce_kernel(const float* __restrict__ x) {
    __shared__ float dpart[8 * 64];
    __shared__ float ss_s[64];
    __shared__ float sa_s[64];
    const int tid = threadIdx.x;
    if (tid < 64) { ss_s[tid] = 0.f; sa_s[tid] = 0.f; }
    __syncthreads();

    const int slab = blockIdx.x >> 3;
    const int p    = blockIdx.x & 7;
    const int warp = tid >> 5;
    const int lane = tid & 31;
    const int q    = warp & 3;
    const int half = warp >> 2;
    const int j    = lane & 15;
    const int u    = lane >> 4;

    const float4* base = reinterpret_cast<const float4*>(x) + (size_t)slab * 65536
                         + (size_t)(8 * p) * 1024 + (16 * q + u) * 16 + j;

    float hreg[8];
#pragma unroll
    for (int i = 0; i < 8; ++i) hreg[i] = 0.f;
    float w0 = 0.f, w1 = 0.f, w2 = 0.f, w3 = 0.f;

#pragma unroll
    for (int dd = 0; dd < 4; ++dd) {
        const int dl = 2 * dd + half;
        const float4* pp = base + dl * 1024;
        float dacc = 0.f;
#pragma unroll
        for (int i = 0; i < 8; ++i) {
            float4 v = __ldcs(pp + i * 32);
            float s0 = v.x * v.x, s1 = v.y * v.y, s2 = v.z * v.z, s3 = v.w * v.w;
            w0 += s0; w1 += s1; w2 += s2; w3 += s3;
            float sm = (s0 + s1) + (s2 + s3);
            hreg[i] += sm;
            dacc    += sm;
        }
        dacc += __shfl_xor_sync(0xffffffffu, dacc, 16);
        if (lane < 16) dpart[dl * 64 + q * 16 + j] = dacc;
    }

#pragma unroll
    for (int i = 0; i < 8; ++i) {
        float v = hreg[i];
        v += __shfl_xor_sync(0xffffffffu, v, 1);
        v += __shfl_xor_sync(0xffffffffu, v, 2);
        v += __shfl_xor_sync(0xffffffffu, v, 4);
        v += __shfl_xor_sync(0xffffffffu, v, 8);
        if (j == 0) atomicAdd(&ss_s[16 * q + u + 2 * i], v);
    }

    atomicAdd(&sa_s[4 * j + 0], w0);
    atomicAdd(&sa_s[4 * j + 1], w1);
    atomicAdd(&sa_s[4 * j + 2], w2);
    atomicAdd(&sa_s[4 * j + 3], w3);

    __syncthreads();

    const int b = slab >> 7;
    const int c = slab & 127;
    if (tid < 32) {
        const int dl = tid >> 2;
        const int qq = tid & 3;
        const float4* dp = reinterpret_cast<const float4*>(&dpart[dl * 64 + qq * 16]);
        float s = 0.f;
#pragma unroll
        for (int k = 0; k < 4; ++k) {
            float4 v = dp[k];
            s += (v.x + v.y) + (v.z + v.w);
        }
        s += __shfl_xor_sync(0xffffffffu, s, 1);
        s += __shfl_xor_sync(0xffffffffu, s, 2);
        if (qq == 0)
            g_feat[(size_t)(b * 192 + 8 * p + dl) * 128 + c] = s * (1.0f / 4096.0f);
    }
    if (tid < 64) {
        redadd(&g_feat[(size_t)(b * 192 + 64 + tid) * 128 + c],
               ss_s[tid] * (1.0f / 4096.0f));
    } else if (tid < 128) {
        const int t = tid - 64;
        redadd(&g_feat[(size_t)(b * 192 + 128 + t) * 128 + c],
               sa_s[t] * (1.0f / 4096.0f));
    }
}

// ---------------------------------------------------------------------------
// FFMA2 SGEMM: tile (64*GM) x (64*GN), BK=16, 256 threads,
// microtile (4*GM)m x (4*GN)n. Double-buffered; B via cp.async (no staging
// regs), A via LDG + transposed STS. Per k-step/warp: GM A-LDS.128 (natural
// f32x2 m-pairs) + GN B-LDS.128 + 4*GN packs + 8*GM*GN FFMA2.
// GM=GN=2: 4 LDS / 32 FFMA2 -> L1 and fma pipes balanced 1:1; with 288-CTA
// grid and <=128 regs (launch_bounds(256,2)) 2 CTAs/SM are resident.
// GEMM1 (GM=GN=1): epilogue bias+relu. GEMM2: partials at C + z*768*768.
// ---------------------------------------------------------------------------
__device__ __forceinline__ void fma2(unsigned long long& d,
                                     unsigned long long a,
                                     unsigned long long b) {
    asm("fma.rn.f32x2 %0, %1, %2, %0;" : "+l"(d) : "l"(a), "l"(b));
}
__device__ __forceinline__ unsigned long long pack2(float v) {
    unsigned long long r;
    asm("mov.b64 %0, {%1, %1};" : "=l"(r) : "f"(v));
    return r;
}
__device__ __forceinline__ float2 u2f(unsigned long long v) {
    float2 f;
    asm("mov.b64 {%0,%1}, %2;" : "=f"(f.x), "=f"(f.y) : "l"(v));
    return f;
}
__device__ __forceinline__ void cp_async16(uint32_t dst, const void* src) {
    asm volatile("cp.async.ca.shared.global [%0], [%1], 16;"
                 :: "r"(dst), "l"(src) : "memory");
}

template <int GM, int GN, bool GEMM1>
__global__ void __launch_bounds__(256, 2) gemm_kernel(const float* __restrict__ A,
                                                      const float* __restrict__ Bw,
                                                      const float* __restrict__ bias,
                                                      float* __restrict__ C,
                                                      int Nn, int K, int Kc) {
    constexpr int AROW = 64 * GM;              // floats per k-row of A stage
    constexpr int BROW = 64 * GN;              // floats per k-row of B stage
    __shared__ float As[2][16][AROW];
    __shared__ float Bs[2][16][BROW];

    const int tid = threadIdx.x;
    const int tx = tid & 15;
    const int ty = tid >> 4;
    const int m0 = blockIdx.y * AROW;
    const int n0 = blockIdx.x * BROW;
    const int kstart = blockIdx.z * Kc;
    const int T = Kc >> 4;

    unsigned long long acc[2 * GM][4 * GN];
#pragma unroll
    for (int i = 0; i < 2 * GM; ++i)
#pragma unroll
        for (int qn = 0; qn < 4 * GN; ++qn) acc[i][qn] = 0ull;

    // staging assignments
    const int a_m = tid >> 2;            // 0..63 (per m-group)
    const int a_f4 = tid & 3;            // which f4 of the 16-k row
    const int b_k = tid >> 4;            // 0..15
    const int b_n4 = tid & 15;           // f4 col (per n-group)

    const float* Ap[GM];
#pragma unroll
    for (int r = 0; r < GM; ++r)
        Ap[r] = A + (size_t)(m0 + 64 * r + a_m) * K + kstart + 4 * a_f4;
    const float* Bp = Bw + (size_t)(kstart + b_k) * Nn + n0 + 4 * b_n4;

    const unsigned as_base = (unsigned)__cvta_generic_to_shared(&As[0][0][0]);
    const unsigned bs_base = (unsigned)__cvta_generic_to_shared(&Bs[0][0][0]);
    const unsigned a_rd = as_base + (unsigned)(ty * 16);
    const unsigned b_rd = bs_base + (unsigned)(tx * 16);
    const unsigned b_wr = bs_base + (unsigned)(b_k * BROW * 4 + b_n4 * 16);
    constexpr unsigned ASTAGE_B = 16 * AROW * 4;
    constexpr unsigned BSTAGE_B = 16 * BROW * 4;

    // prologue: tile 0
#pragma unroll
    for (int g = 0; g < GN; ++g)
        cp_async16(b_wr + (unsigned)(g * 256), Bp + 64 * g);
    asm volatile("cp.async.commit_group;" ::: "memory");
    float4 pa[GM];
#pragma unroll
    for (int r = 0; r < GM; ++r) pa[r] = *reinterpret_cast<const float4*>(Ap[r]);
#pragma unroll
    for (int r = 0; r < GM; ++r) {
        float* aw = &As[0][0][0] + (4 * a_f4) * AROW + (64 * r + a_m);
        aw[0]        = pa[r].x;
        aw[AROW]     = pa[r].y;
        aw[2 * AROW] = pa[r].z;
        aw[3 * AROW] = pa[r].w;
    }
    asm volatile("cp.async.wait_group 0;" ::: "memory");
    __syncthreads();

    for (int t = 0; ; ) {
        const int st = t & 1;
        const int ns = st ^ 1;
        const bool more = (t + 1 < T);
        if (more) {
#pragma unroll
            for (int g = 0; g < GN; ++g)
                cp_async16(b_wr + (unsigned)(ns * BSTAGE_B + g * 256),
                           Bp + (size_t)(t + 1) * 16 * Nn + 64 * g);
            asm volatile("cp.async.commit_group;" ::: "memory");
#pragma unroll
            for (int r = 0; r < GM; ++r)
                pa[r] = *reinterpret_cast<const float4*>(Ap[r] + (t + 1) * 16);
        }

        const unsigned ao = a_rd + (unsigned)(st * ASTAGE_B);
        const unsigned bo = b_rd + (unsigned)(st * BSTAGE_B);
#pragma unroll
        for (int k = 0; k < 16; ++k) {
            unsigned long long am[2 * GM];
            float bf[4 * GN];
#pragma unroll
            for (int g = 0; g < GM; ++g)
                asm volatile("ld.shared.v2.b64 {%0,%1},[%2];"
                             : "=l"(am[2 * g]), "=l"(am[2 * g + 1])
                             : "r"(ao + (unsigned)(k * AROW * 4 + g * 256)));
#pragma unroll
            for (int g = 0; g < GN; ++g)
                asm volatile("ld.shared.v4.f32 {%0,%1,%2,%3},[%4];"
                             : "=f"(bf[4 * g]), "=f"(bf[4 * g + 1]),
                               "=f"(bf[4 * g + 2]), "=f"(bf[4 * g + 3])
                             : "r"(bo + (unsigned)(k * BROW * 4 + g * 256)));
            unsigned long long bb[4 * GN];
#pragma unroll
            for (int qn = 0; qn < 4 * GN; ++qn) bb[qn] = pack2(bf[qn]);
#pragma unroll
            for (int i = 0; i < 2 * GM; ++i) {
#pragma unroll
                for (int qn = 0; qn < 4 * GN; ++qn) fma2(acc[i][qn], am[i], bb[qn]);
            }
        }

        if (!more) break;
#pragma unroll
        for (int r = 0; r < GM; ++r) {
            float* aw = &As[ns][0][0] + (4 * a_f4) * AROW + (64 * r + a_m);
            aw[0]        = pa[r].x;
            aw[AROW]     = pa[r].y;
            aw[2 * AROW] = pa[r].z;
            aw[3 * AROW] = pa[r].w;
        }
        asm volatile("cp.async.wait_group 0;" ::: "memory");
        __syncthreads();
        ++t;
    }

    // epilogue: acc[i][qn], i = 2g+p -> row m0 + 64g + 4ty + 2p (+1 for .y);
    // qn = 4gn+q -> col n0 + 64gn + 4tx + q.
    if (GEMM1) {
#pragma unroll
        for (int i = 0; i < 2 * GM; ++i) {
            const int mrow = m0 + 64 * (i >> 1) + 4 * ty + 2 * (i & 1);
#pragma unroll
            for (int gn = 0; gn < GN; ++gn) {
                float4 bl = *reinterpret_cast<const float4*>(&bias[n0 + 64 * gn + 4 * tx]);
                float2 f0 = u2f(acc[i][4 * gn + 0]);
                float2 f1 = u2f(acc[i][4 * gn + 1]);
                float2 f2 = u2f(acc[i][4 * gn + 2]);
                float2 f3 = u2f(acc[i][4 * gn + 3]);
                float4 lo0 = make_float4(fmaxf(f0.x + bl.x, 0.f), fmaxf(f1.x + bl.y, 0.f),
                                         fmaxf(f2.x + bl.z, 0.f), fmaxf(f3.x + bl.w, 0.f));
                float4 lo1 = make_float4(fmaxf(f0.y + bl.x, 0.f), fmaxf(f1.y + bl.y, 0.f),
                                         fmaxf(f2.y + bl.z, 0.f), fmaxf(f3.y + bl.w, 0.f));
                *reinterpret_cast<float4*>(&C[(size_t)mrow * Nn + n0 + 64 * gn + 4 * tx]) = lo0;
                *reinterpret_cast<float4*>(&C[(size_t)(mrow + 1) * Nn + n0 + 64 * gn + 4 * tx]) = lo1;
            }
        }
    } else {
        float* Cout = C + (size_t)blockIdx.z * 768 * 768;
#pragma unroll
        for (int i = 0; i < 2 * GM; ++i) {
            const int mrow = m0 + 64 * (i >> 1) + 4 * ty + 2 * (i & 1);
#pragma unroll
            for (int gn = 0; gn < GN; ++gn) {
                float2 f0 = u2f(acc[i][4 * gn + 0]);
                float2 f1 = u2f(acc[i][4 * gn + 1]);
                float2 f2 = u2f(acc[i][4 * gn + 2]);
                float2 f3 = u2f(acc[i][4 * gn + 3]);
                float4 lo0 = make_float4(f0.x, f1.x, f2.x, f3.x);
                float4 lo1 = make_float4(f0.y, f1.y, f2.y, f3.y);
                *reinterpret_cast<float4*>(&Cout[(size_t)mrow * Nn + n0 + 64 * gn + 4 * tx]) = lo0;
                *reinterpret_cast<float4*>(&Cout[(size_t)(mrow + 1) * Nn + n0 + 64 * gn + 4 * tx]) = lo1;
            }
        }
    }
}

// ---------------------------------------------------------------------------
// Combine split-K=8 partials + bias; 2 float4/thread, 8-deep MLP per f4.
// ---------------------------------------------------------------------------
__global__ void __launch_bounds__(256) combine_kernel(const float* __restrict__ part,
                                                      const float* __restrict__ bias,
                                                      float* __restrict__ out) {
    const float4* p = reinterpret_cast<const float4*>(part);
#pragma unroll
    for (int rep = 0; rep < 2; ++rep) {
        const int i = blockIdx.x * 512 + rep * 256 + threadIdx.x;
        float4 v[8];
#pragma unroll
        for (int z = 0; z < 8; ++z) v[z] = p[i + z * 147456];
        float4 bb = reinterpret_cast<const float4*>(bias)[i % 192];
        float4 r;
        r.x = (((v[0].x + v[1].x) + (v[2].x + v[3].x)) +
               ((v[4].x + v[5].x) + (v[6].x + v[7].x))) + bb.x;
        r.y = (((v[0].y + v[1].y) + (v[2].y + v[3].y)) +
               ((v[4].y + v[5].y) + (v[6].y + v[7].y))) + bb.y;
        r.z = (((v[0].z + v[1].z) + (v[2].z + v[3].z)) +
               ((v[4].z + v[5].z) + (v[6].z + v[7].z))) + bb.z;
        r.w = (((v[0].w + v[1].w) + (v[2].w + v[3].w)) +
               ((v[4].w + v[5].w) + (v[6].w + v[7].w))) + bb.w;
        reinterpret_cast<float4*>(out)[i] = r;
    }
}

// ---------------------------------------------------------------------------
extern "C" void kernel_launch(void* const* d_in, const int* in_sizes, int n_in,
                              void* d_out, int out_size) {
    const float* x  = (const float*)d_in[0];
    const float* W1 = (const float*)d_in[1];
    const float* b1 = (const float*)d_in[2];
    const float* W2 = (const float*)d_in[3];
    const float* b2 = (const float*)d_in[4];
    float* out = (float*)d_out;

    float* feat = nullptr;
    float* hbuf = nullptr;
    float* part = nullptr;
    cudaGetSymbolAddress((void**)&feat, g_feat);
    cudaGetSymbolAddress((void**)&hbuf, g_hbuf);
    cudaGetSymbolAddress((void**)&part, g_part);

    // 0) zero g_feat (h/w planes are RED targets)
    init_feat<<<96, 256>>>();

    // 1) reduction: 4096 CTAs (1/8 slab each)
    reduce_kernel<<<4096, 256>>>(x);

    // 2) h = relu(feat @ W1 + b1): tile 64x64 -> grid 24x12 = 288 CTAs
    gemm_kernel<1, 1, true><<<dim3(24, 12, 1), 256>>>(feat, W1, b1, hbuf,
                                                      1536, 128, 128);

    // 3) partials = h @ W2 (split-K=8): tile 128x128 -> 6x6x8 = 288 CTAs,
    //    2 CTAs/SM resident
    gemm_kernel<2, 2, false><<<dim3(6, 6, 8), 256>>>(hbuf, W2, nullptr, part,
                                                     768, 1536, 192);

    // 4) out = sum(8 partials) + b2
    combine_kernel<<<288, 256>>>(part, b2, out);
}